// round 15
// baseline (speedup 1.0000x reference)
#include <cuda_runtime.h>
#include <math.h>
#include <stdint.h>
#include <stddef.h>

// Problem constants (VanillaRNN_30623116821140)
#define T_STEPS 2048
#define BATCH   64
#define NIN     128
#define NHID    512
#define NOUT    64

#define CPG 8   // CTAs per cluster (column slices of 64)
#define BPC 4   // batch rows per cluster
#define STEP_BH (BATCH * NHID)   // 32768 floats per timestep

// Scan dynamic smem:
//   sWT [64][516]      W_hh slice TRANSPOSED (k-contiguous per column);
//                      stride 516 -> conflict-free float4 loads, 16B aligned
//   sHT [2][4][512]    h double-buffer, [buf][row][k]
//   + 128 floats pad   (pipeline over-read safety)
#define W_STRIDE 516
#define SHT_BUF_FLOATS (BPC * NHID)                   // 2048
#define SCAN_SMEM_FLOATS (64 * W_STRIDE + 2 * SHT_BUF_FLOATS + 128)
#define SCAN_SMEM_BYTES  (SCAN_SMEM_FLOATS * 4)       // 149,504 B

// ---------------------------------------------------------------------------
// XLA EmitFastTanh — exact port (bit-validated: rel_err == 0.0 since R8)
// ---------------------------------------------------------------------------
__device__ __forceinline__ float xla_tanh(float x) {
    const float kClamp = 7.99881172180175781f;
    float ax = fabsf(x);
    float xc = fminf(fmaxf(x, -kClamp), kClamp);
    float x2 = __fmul_rn(xc, xc);
    float np;
    np = -2.76076847742355e-16f;
    np = fmaf(np, x2, 2.00018790482477e-13f);
    np = fmaf(np, x2, -8.60467152213735e-11f);
    np = fmaf(np, x2, 5.12229709037114e-08f);
    np = fmaf(np, x2, 1.48572235717979e-05f);
    np = fmaf(np, x2, 6.37261928875436e-04f);
    np = fmaf(np, x2, 4.89352455891786e-03f);
    float num = __fmul_rn(xc, np);
    float dp;
    dp = 1.19825839466702e-06f;
    dp = fmaf(dp, x2, 1.18534705686654e-04f);
    dp = fmaf(dp, x2, 2.26843463243900e-03f);
    dp = fmaf(dp, x2, 4.89352518554385e-03f);
    float r = __fdiv_rn(num, dp);
    return (ax < 0.0004f) ? x : r;
}

// ---------------------------------------------------------------------------
// PTX helpers
// ---------------------------------------------------------------------------
__device__ __forceinline__ uint32_t smem_u32(const void* p) {
    uint32_t a;
    asm("{ .reg .u64 t; cvta.to.shared.u64 t, %1; cvt.u32.u64 %0, t; }"
        : "=r"(a) : "l"(p));
    return a;
}
__device__ __forceinline__ uint32_t ctarank() {
    uint32_t r; asm("mov.u32 %0, %%cluster_ctarank;" : "=r"(r)); return r;
}
__device__ __forceinline__ void mbar_init(uint32_t addr, uint32_t count) {
    asm volatile("mbarrier.init.shared.b64 [%0], %1;" :: "r"(addr), "r"(count) : "memory");
}
__device__ __forceinline__ void mbar_arrive_peer(uint32_t addr, uint32_t peer) {
    asm volatile(
        "{ .reg .b32 r; mapa.shared::cluster.u32 r, %0, %1;\n\t"
        "mbarrier.arrive.release.cluster.shared::cluster.b64 _, [r]; }"
        :: "r"(addr), "r"(peer) : "memory");
}
__device__ __forceinline__ void mbar_wait(uint32_t addr, uint32_t parity) {
    uint32_t done;
    do {
        asm volatile(
            "{ .reg .pred p;\n\t"
            "mbarrier.try_wait.parity.acquire.cluster.shared::cta.b64 p, [%1], %2, 0x989680;\n\t"
            "selp.b32 %0, 1, 0, p; }"
            : "=r"(done) : "r"(addr), "r"(parity) : "memory");
    } while (!done);
}
__device__ __forceinline__ void cluster_sync_() {
    asm volatile("barrier.cluster.arrive.aligned;" ::: "memory");
    asm volatile("barrier.cluster.wait.aligned;" ::: "memory");
}
__device__ __forceinline__ uint32_t mapa_peer(uint32_t local_addr, uint32_t peer) {
    uint32_t r;
    asm("mapa.shared::cluster.u32 %0, %1, %2;" : "=r"(r) : "r"(local_addr), "r"(peer));
    return r;
}
__device__ __forceinline__ void dsmem_st32(uint32_t raddr, float v) {
    asm volatile("st.shared::cluster.b32 [%0], %1;" :: "r"(raddr), "f"(v) : "memory");
}

// ---------------------------------------------------------------------------
// Kernel 1: ux = u @ W_uh + b_hh (bit-exact; unchanged since R9)
// ---------------------------------------------------------------------------
__global__ __launch_bounds__(256) void k_ux(const float* __restrict__ u,
                                            const float* __restrict__ W_uh,
                                            const float* __restrict__ b_hh,
                                            float* __restrict__ hall) {
    __shared__ float sU[64][132];
    const int tid = threadIdx.x;
    const int m0  = blockIdx.y * 64;
    const int c0  = blockIdx.x * 64;

    for (int idx = tid; idx < 64 * 32; idx += 256) {
        int r = idx >> 5, q = (idx & 31) << 2;
        *(float4*)(&sU[r][q]) = *(const float4*)(u + (size_t)(m0 + r) * NIN + q);
    }
    __syncthreads();

    const int tr = tid >> 4;
    const int tc = tid & 15;

    float acc[4][4];
#pragma unroll
    for (int i = 0; i < 4; ++i)
#pragma unroll
        for (int j = 0; j < 4; ++j) acc[i][j] = 0.f;

#pragma unroll 4
    for (int k = 0; k < NIN; ++k) {
        float4 w = *(const float4*)(W_uh + (size_t)k * NHID + c0 + tc * 4);
#pragma unroll
        for (int i = 0; i < 4; ++i) {
            float a = sU[tr * 4 + i][k];
            acc[i][0] = fmaf(a, w.x, acc[i][0]);
            acc[i][1] = fmaf(a, w.y, acc[i][1]);
            acc[i][2] = fmaf(a, w.z, acc[i][2]);
            acc[i][3] = fmaf(a, w.w, acc[i][3]);
        }
    }

    float4 b = *(const float4*)(b_hh + c0 + tc * 4);
#pragma unroll
    for (int i = 0; i < 4; ++i) {
        float4 v = make_float4(__fadd_rn(acc[i][0], b.x), __fadd_rn(acc[i][1], b.y),
                               __fadd_rn(acc[i][2], b.z), __fadd_rn(acc[i][3], b.w));
        *(float4*)(hall + (size_t)(m0 + tr * 4 + i) * NHID + c0 + tc * 4) = v;
    }
}

// ---------------------------------------------------------------------------
// Kernel 2: persistent scan — 256 threads (2 warps/SMSP), ONE row per thread,
// transposed W in smem (2x LDS.128 per 8k instead of 8 scalar LDS).
// Arithmetic bit-identical: each output = ONE ascending-k fmaf chain.
// Thread (row = tid>>6, c = tid&63) owns row r0+row of column cs+c.
// h layout: sHT[buf][row][k]  (broadcast float4 reads within a warp).
// ---------------------------------------------------------------------------
__global__ __launch_bounds__(256) __cluster_dims__(CPG, 1, 1)
void k_scan(const float* __restrict__ W_hh, float* __restrict__ hall) {
    extern __shared__ float sm[];
    float* sWT = sm;                    // [64][516]
    float* sHT = sm + 64 * W_STRIDE;    // [2][4][512]  (+128 pad after)
    __shared__ __align__(8) unsigned long long mbar_s;

    const int tid  = threadIdx.x;
    const uint32_t rank = ctarank();
    const int cs   = (int)rank * 64;
    const int r0   = (blockIdx.x / CPG) * BPC;
    const uint32_t mb = smem_u32(&mbar_s);

    if (tid == 0) mbar_init(mb, CPG);

    // Load W slice TRANSPOSED: sWT[c][k] = W_hh[k][cs+c]
    for (int i = tid; i < NHID * 64; i += 256) {
        int k = i >> 6, cc = i & 63;
        sWT[cc * W_STRIDE + k] = W_hh[(size_t)k * NHID + cs + cc];
    }

    const int row = tid >> 6;            // 0..3
    const int c   = tid & 63;            // 0..63
    const int r   = r0 + row;
    const size_t off = (size_t)r * NHID + cs + c;

    // Remote DSMEM addresses of this thread's h slot in buf 0 of all 8 CTAs:
    // sHT[0][row][cs+c]  (4 B). buf1 = +8192 B on the same peer.
    uint32_t dst0 = smem_u32(sHT) + (uint32_t)((row * NHID + cs + c) * 4);
    uint32_t rdst[CPG];
#pragma unroll
    for (int j = 0; j < CPG; ++j) rdst[j] = mapa_peer(dst0, (uint32_t)j);

    cluster_sync_();   // mbarriers visible; W loaded

    // ---- t = 0 : h_0 = xla_tanh(ux_0) ----
    float h = xla_tanh(hall[off]);
#pragma unroll
    for (int j = 0; j < CPG; ++j) dsmem_st32(rdst[j], h);   // buf 0
    __syncthreads();
    if (tid < CPG) mbar_arrive_peer(mb, tid);
    hall[off] = h;

    // Prefetch ux_1
    float ux = hall[(size_t)STEP_BH + off];

    const float* wRow = sWT + c * W_STRIDE;   // thread's W column, k-contiguous

    uint32_t parity = 0;
    for (int t = 1; t < T_STEPS; ++t) {
        mbar_wait(mb, parity);
        parity ^= 1u;

        // Prefetch ux_{t+1} (hidden under compute)
        float nux = 0.f;
        if (t + 1 < T_STEPS) nux = hall[(size_t)(t + 1) * STEP_BH + off];

        const float* hp = sHT + ((t - 1) & 1) * SHT_BUF_FLOATS + row * NHID;

        // -------- software-pipelined ascending-k chain (blocks of 8 k) ----
        // Loads reordered only; the single-accumulator fmaf order is k=0..511.
        // Over-reads one block past k=511 into padded smem (never used).
        float4 wA0 = *(const float4*)(wRow + 0);
        float4 wA1 = *(const float4*)(wRow + 4);
        float4 hA0 = *(const float4*)(hp + 0);
        float4 hA1 = *(const float4*)(hp + 4);

        float a = 0.f;

#pragma unroll 1
        for (int blk = 0; blk < 64; blk += 2) {
            const int k1 = (blk + 1) * 8;
            float4 wB0 = *(const float4*)(wRow + k1);
            float4 wB1 = *(const float4*)(wRow + k1 + 4);
            float4 hB0 = *(const float4*)(hp + k1);
            float4 hB1 = *(const float4*)(hp + k1 + 4);

            a = fmaf(hA0.x, wA0.x, a);
            a = fmaf(hA0.y, wA0.y, a);
            a = fmaf(hA0.z, wA0.z, a);
            a = fmaf(hA0.w, wA0.w, a);
            a = fmaf(hA1.x, wA1.x, a);
            a = fmaf(hA1.y, wA1.y, a);
            a = fmaf(hA1.z, wA1.z, a);
            a = fmaf(hA1.w, wA1.w, a);

            const int k2 = (blk + 2) * 8;   // last iter: padded over-read
            wA0 = *(const float4*)(wRow + k2);
            wA1 = *(const float4*)(wRow + k2 + 4);
            hA0 = *(const float4*)(hp + k2);
            hA1 = *(const float4*)(hp + k2 + 4);

            a = fmaf(hB0.x, wB0.x, a);
            a = fmaf(hB0.y, wB0.y, a);
            a = fmaf(hB0.z, wB0.z, a);
            a = fmaf(hB0.w, wB0.w, a);
            a = fmaf(hB1.x, wB1.x, a);
            a = fmaf(hB1.y, wB1.y, a);
            a = fmaf(hB1.z, wB1.z, a);
            a = fmaf(hB1.w, wB1.w, a);
        }

        h = xla_tanh(__fadd_rn(a, ux));

        // Broadcast h_t into buf (t&1) of all 8 cluster CTAs
        uint32_t boff = (uint32_t)((t & 1) * (SHT_BUF_FLOATS * 4));
#pragma unroll
        for (int j = 0; j < CPG; ++j) dsmem_st32(rdst[j] + boff, h);
        __syncthreads();
        if (tid < CPG) mbar_arrive_peer(mb, tid);

        // Off critical path: h_all output + ux rotate
        hall[(size_t)t * STEP_BH + off] = h;
        ux = nux;
    }

    cluster_sync_();
}

// ---------------------------------------------------------------------------
// Kernel 3: logits = h_{T-1} @ W_hy + b_hy (proven bit-exact)
// ---------------------------------------------------------------------------
__global__ __launch_bounds__(256) void k_logits(const float* __restrict__ hall,
                                                const float* __restrict__ W_hy,
                                                const float* __restrict__ b_hy,
                                                float* __restrict__ logits) {
    const int tid = threadIdx.x;
    const int b = blockIdx.x * 4 + (tid >> 6);
    const int o = tid & 63;
    const float* hr = hall + (size_t)(T_STEPS - 1) * STEP_BH + (size_t)b * NHID;
    float acc = 0.f;
#pragma unroll 4
    for (int h = 0; h < NHID; ++h)
        acc = fmaf(__ldg(hr + h), __ldg(W_hy + (size_t)h * NOUT + o), acc);
    logits[b * NOUT + o] = __fadd_rn(acc, __ldg(b_hy + o));
}

// ---------------------------------------------------------------------------
extern "C" void kernel_launch(void* const* d_in, const int* in_sizes, int n_in,
                              void* d_out, int out_size) {
    const float *u = 0, *W_uh = 0, *W_hh = 0, *W_hy = 0, *b_hh = 0, *b_hy = 0;
    for (int i = 0; i < n_in; ++i) {
        switch (in_sizes[i]) {
            case 16777216: u    = (const float*)d_in[i]; break; // 2048*64*128
            case 262144:   W_hh = (const float*)d_in[i]; break; // 512*512
            case 65536:    W_uh = (const float*)d_in[i]; break; // 128*512
            case 32768:    W_hy = (const float*)d_in[i]; break; // 512*64
            case 512:      b_hh = (const float*)d_in[i]; break;
            case 64:       b_hy = (const float*)d_in[i]; break;
            default: break;
        }
    }

    // Output layout A (proven): [logits | h_all]
    float* out    = (float*)d_out;
    float* logits = out;
    float* hall   = out + (size_t)BATCH * NOUT;
    (void)out_size;

    cudaFuncSetAttribute(k_scan, cudaFuncAttributeMaxDynamicSharedMemorySize,
                         SCAN_SMEM_BYTES);

    k_ux<<<dim3(NHID / 64, (T_STEPS * BATCH) / 64), 256>>>(u, W_uh, b_hh, hall);
    k_scan<<<16 * CPG, 256, SCAN_SMEM_BYTES>>>(W_hh, hall);
    k_logits<<<BATCH / 4, 256>>>(hall, W_hy, b_hy, logits);
}